// round 9
// baseline (speedup 1.0000x reference)
#include <cuda_runtime.h>

#define NP      3072
#define SPLITS  37
#define CHUNK   84              // 37*84 = 3108 >= 3072 (padded)
#define HC      (CHUNK / 2)     // 42 packed iterations
#define TPB     128
#define JBLK    (NP / TPB)      // 24 -> grid = 24*37 = 888 = 6*148 blocks
#define TOTB    (JBLK * SPLITS) // 888 blocks
#define JPT     (NP / TPB)      // 24 j's per thread in the fused epilogue

// constants (sigma = 1, A = 1/sqrt(2), A^2 = 1/2)
#define A_CONST 0.7071067811865476f
#define C1      0.7978845608028654f     // 2A/sqrt(pi) == 4A^3/sqrt(pi) since A^2=1/2
#define NC      14.399645f              // 90.4756 / (2*pi)
// Abramowitz-Stegun 7.1.26 erfc: erfc(x) = g*t*P(t), t=1/(1+p*x), |err|<=1.5e-7
#define P_AS  0.3275911f
#define PA    (P_AS * A_CONST)
#define AS1   0.254829592f
#define AS2  -0.284496736f
#define AS3   1.421413741f
#define AS4  -1.453152027f
#define AS5   1.061405429f
#define NL2E_HALF (-0.7213475204444817f)  // -0.5*log2(e)
#define RCUT2     20.25f                   // beyond this erf=1,g=0 to ~1e-4 rel
#define RINV_CUT  0.2222f                  // 1/sqrt(RCUT2)

typedef unsigned long long u64;

__device__ float g_acc[6 * NP];   // per-j accumulators (REDG targets)
__device__ int   g_sem;

__device__ __forceinline__ float rcp_fast(float x) {
    float y; asm("rcp.approx.f32 %0, %1;" : "=f"(y) : "f"(x)); return y;
}
__device__ __forceinline__ float ex2_fast(float x) {
    float y; asm("ex2.approx.f32 %0, %1;" : "=f"(y) : "f"(x)); return y;
}
__device__ __forceinline__ u64 pk(float lo, float hi) {
    u64 r; asm("mov.b64 %0, {%1, %2};" : "=l"(r) : "f"(lo), "f"(hi)); return r;
}
__device__ __forceinline__ void upk(u64 a, float& lo, float& hi) {
    asm("mov.b64 {%0, %1}, %2;" : "=f"(lo), "=f"(hi) : "l"(a));
}
__device__ __forceinline__ u64 fma2(u64 a, u64 b, u64 c) {
    u64 d; asm("fma.rn.f32x2 %0, %1, %2, %3;" : "=l"(d) : "l"(a), "l"(b), "l"(c)); return d;
}
__device__ __forceinline__ u64 mul2(u64 a, u64 b) {
    u64 d; asm("mul.rn.f32x2 %0, %1, %2;" : "=l"(d) : "l"(a), "l"(b)); return d;
}
__device__ __forceinline__ u64 add2(u64 a, u64 b) {
    u64 d; asm("add.rn.f32x2 %0, %1, %2;" : "=l"(d) : "l"(a), "l"(b)); return d;
}

// scalar correction for one near pair: add (true - bare) terms; everything ~ g
__device__ __forceinline__ void corr_half(
    float dx, float dy, float dz, float qi,
    float ux, float uy, float uz, bool act,
    float& A1, float& A2,
    float& Hx, float& Hy, float& Hz,
    float& Wx, float& Wy, float& Wz,
    float& Gx, float& Gy, float& Gz)
{
    float t0 = dx * dx;
    t0 = fmaf(dy, dy, t0);
    const float d2 = fmaf(dz, dz, t0);
    const bool on = act && (d2 != 0.f) && (d2 < RCUT2);
    const float d2s  = fmaxf(d2, 1e-8f);
    const float rinv = rsqrtf(d2s);
    const float m    = on ? 1.f : 0.f;
    const float g    = ex2_fast(NL2E_HALF * d2s) * m;
    const float rn   = d2s * rinv;
    const float tt   = rcp_fast(fmaf(PA, rn, 1.f));
    const float poly = fmaf(fmaf(fmaf(fmaf(AS5, tt, AS4), tt, AS3), tt, AS2), tt, AS1);
    const float erfc = g * tt * poly;
    const float de   = -erfc * rinv;
    const float rr   = rinv * rinv;
    const float c1g  = C1 * g;
    const float ds1  = (de - c1g) * rr;
    const float uri  = fmaf(ux, dx, fmaf(uy, dy, uz * dz));
    const float ds2r = fmaf(3.f, ds1, -c1g) * (uri * rr);
    A1 = fmaf(qi, de, A1);
    A2 = fmaf(ds1, uri, A2);
    Hx = fmaf(ds2r, dx, Hx); Hy = fmaf(ds2r, dy, Hy); Hz = fmaf(ds2r, dz, Hz);
    const float qd = qi * ds1;
    Wx = fmaf(qd, dx, Wx); Wy = fmaf(qd, dy, Wy); Wz = fmaf(qd, dz, Wz);
    Gx = fmaf(ds1, ux, Gx); Gy = fmaf(ds1, uy, Gy); Gz = fmaf(ds1, uz, Gz);
}

__global__ __launch_bounds__(TPB, 6)
void ewald_pair_kernel(const float* __restrict__ q,
                       const float* __restrict__ r,
                       const float* __restrict__ u,
                       const float* __restrict__ kappa,
                       const float* __restrict__ alpha,
                       float* __restrict__ out)
{
    const int j  = blockIdx.x * TPB + threadIdx.x;
    const int s  = blockIdx.y;
    const int i0 = s * CHUNK;

    __shared__ ulonglong2 s_p0[HC];   // {-rx2, -ry2}
    __shared__ ulonglong2 s_p1[HC];   // {-rz2,   q2}
    __shared__ ulonglong2 s_p2[HC];   // { ux2,  uy2}
    __shared__ u64        s_p3[HC];   // { uz2 }

    for (int t = threadIdx.x; t < HC; t += TPB) {
        const int ia = i0 + t;
        const int ib = ia + HC;
        float rxa, rya, rza, qa, uxa, uya, uza;
        float rxb, ryb, rzb, qb, uxb, uyb, uzb;
        if (ia < NP) {
            rxa = r[3*ia+0]; rya = r[3*ia+1]; rza = r[3*ia+2];
            qa = q[ia]; uxa = u[3*ia+0]; uya = u[3*ia+1]; uza = u[3*ia+2];
        } else { rxa=1e4f; rya=1e4f; rza=1e4f; qa=0.f; uxa=0.f; uya=0.f; uza=0.f; }
        if (ib < NP) {
            rxb = r[3*ib+0]; ryb = r[3*ib+1]; rzb = r[3*ib+2];
            qb = q[ib]; uxb = u[3*ib+0]; uyb = u[3*ib+1]; uzb = u[3*ib+2];
        } else { rxb=1e4f; ryb=1e4f; rzb=1e4f; qb=0.f; uxb=0.f; uyb=0.f; uzb=0.f; }
        s_p0[t] = make_ulonglong2(pk(-rxa, -rxb), pk(-rya, -ryb));
        s_p1[t] = make_ulonglong2(pk(-rza, -rzb), pk(qa, qb));
        s_p2[t] = make_ulonglong2(pk(uxa, uxb), pk(uya, uyb));
        s_p3[t] = pk(uza, uzb);
    }
    __syncthreads();

    const float rjx = r[3*j+0], rjy = r[3*j+1], rjz = r[3*j+2];
    const float ujx = u[3*j+0], ujy = u[3*j+1], ujz = u[3*j+2];

    const u64 rjx2 = pk(rjx, rjx), rjy2 = pk(rjy, rjy), rjz2 = pk(rjz, rjz);
    const u64 kThree = 0x4040000040400000ull;

    u64 a1 = 0, a2 = 0;
    u64 hx = 0, hy = 0, hz = 0;
    u64 wx = 0, wy = 0, wz = 0;
    u64 gx = 0, gy = 0, gz = 0;
    u64 mask = 0;

    // ---------------- Pass A: bare Coulomb (erf=1, g=0) for ALL pairs ----------------
#pragma unroll 6
    for (int t = 0; t < HC; ++t) {
        const ulonglong2 p0 = s_p0[t];
        const ulonglong2 p1 = s_p1[t];
        const ulonglong2 p2 = s_p2[t];
        const u64 uz2 = s_p3[t];

        const u64 dx = add2(rjx2, p0.x);
        const u64 dy = add2(rjy2, p0.y);
        const u64 dz = add2(rjz2, p1.x);
        u64 d2 = mul2(dx, dx);
        d2 = fma2(dy, dy, d2);
        d2 = fma2(dz, dz, d2);

        float d2l, d2h; upk(d2, d2l, d2h);
        float rl = rsqrtf(d2l), rh = rsqrtf(d2h);
        rl = (d2l == 0.f) ? 0.f : rl;
        rh = (d2h == 0.f) ? 0.f : rh;
        const bool near = fmaxf(rl, rh) > RINV_CUT;
        mask |= ((u64)near) << t;

        const u64 rinv = pk(rl, rh);
        const u64 rr   = mul2(rinv, rinv);
        const u64 s1   = mul2(rinv, rr);

        a1 = fma2(p1.y, rinv, a1);

        u64 uri = mul2(p2.x, dx);
        uri = fma2(p2.y, dy, uri);
        uri = fma2(uz2, dz, uri);
        a2 = fma2(s1, uri, a2);

        const u64 v   = mul2(uri, rr);
        const u64 v3  = mul2(v, kThree);
        const u64 s2r = mul2(s1, v3);

        hx = fma2(s2r, dx, hx);
        hy = fma2(s2r, dy, hy);
        hz = fma2(s2r, dz, hz);
        const u64 qs1 = mul2(p1.y, s1);
        wx = fma2(qs1, dx, wx);
        wy = fma2(qs1, dy, wy);
        wz = fma2(qs1, dz, wz);
        gx = fma2(s1, p2.x, gx);
        gy = fma2(s1, p2.y, gy);
        gz = fma2(s1, uz2, gz);
    }

    float l, h;
    upk(a1, l, h); float A1 = l + h;
    upk(a2, l, h); float A2 = l + h;
    upk(hx, l, h); float Hx = l + h;
    upk(hy, l, h); float Hy = l + h;
    upk(hz, l, h); float Hz = l + h;
    upk(wx, l, h); float Wx = l + h;
    upk(wy, l, h); float Wy = l + h;
    upk(wz, l, h); float Wz = l + h;
    upk(gx, l, h); float Gx = l + h;
    upk(gy, l, h); float Gy = l + h;
    upk(gz, l, h); float Gz = l + h;

    // ---------------- Pass B: sparse erf/gauss corrections for near pairs ----------------
    unsigned mlo = (unsigned)mask;
    unsigned mhi = (unsigned)(mask >> 32);
    while (__any_sync(0xFFFFFFFFu, mlo | mhi)) {
        const bool act = (mlo | mhi) != 0u;
        int t = 0;
        if (mlo) { t = __ffs(mlo) - 1;  mlo &= mlo - 1u; }
        else if (mhi) { t = __ffs(mhi) + 31; mhi &= mhi - 1u; }

        const ulonglong2 p0 = s_p0[t];
        const ulonglong2 p1 = s_p1[t];
        const ulonglong2 p2 = s_p2[t];
        const u64 uz2 = s_p3[t];
        float nrxl, nrxh, nryl, nryh, nrzl, nrzh, ql, qh;
        float uxl, uxh, uyl, uyh, uzl, uzh;
        upk(p0.x, nrxl, nrxh); upk(p0.y, nryl, nryh);
        upk(p1.x, nrzl, nrzh); upk(p1.y, ql, qh);
        upk(p2.x, uxl, uxh);   upk(p2.y, uyl, uyh);
        upk(uz2, uzl, uzh);

        corr_half(rjx + nrxl, rjy + nryl, rjz + nrzl, ql, uxl, uyl, uzl, act,
                  A1, A2, Hx, Hy, Hz, Wx, Wy, Wz, Gx, Gy, Gz);
        corr_half(rjx + nrxh, rjy + nryh, rjz + nrzh, qh, uxh, uyh, uzh, act,
                  A1, A2, Hx, Hy, Hz, Wx, Wy, Wz, Gx, Gy, Gz);
    }

    const float Mx = Hx - Gx, My = Hy - Gy, Mz = Hz - Gz;
    const float fx = Wx + Mx, fy = Wy + My, fz = Wz + Mz;
    const float dd = ujx * Mx + ujy * My + ujz * Mz;

    // ---------------- accumulate into global per-j sums (REDG, no return) ----------------
    atomicAdd(&g_acc[0*NP + j], A1);
    atomicAdd(&g_acc[1*NP + j], A2);
    atomicAdd(&g_acc[2*NP + j], fx);
    atomicAdd(&g_acc[3*NP + j], fy);
    atomicAdd(&g_acc[4*NP + j], fz);
    atomicAdd(&g_acc[5*NP + j], dd);
    __threadfence();   // release: my REDGs visible before the semaphore bump
    __syncthreads();

    __shared__ bool lastblk;
    if (threadIdx.x == 0) {
        const int old = atomicAdd(&g_sem, 1);
        lastblk = (old == TOTB - 1);
    }
    __syncthreads();
    if (!lastblk) return;

    // ---------------- fused epilogue: last block processes all j ----------------
    __threadfence();   // acquire
    const int tid = threadIdx.x;
    float pot = 0.f;
#pragma unroll 4
    for (int g2 = 0; g2 < JPT; ++g2) {
        const int j2 = g2 * TPB + tid;
        const float a1v = g_acc[0*NP + j2];
        const float a2v = g_acc[1*NP + j2];
        const float fxv = g_acc[2*NP + j2];
        const float fyv = g_acc[3*NP + j2];
        const float fzv = g_acc[4*NP + j2];
        const float ddv = g_acc[5*NP + j2];

        const float ka = kappa[j2];
        const float al = alpha[j2];
        const float qj = q[j2];

        const float ephi = NC * (a1v + a2v);
        const float qind = -ka * ephi;
        const float efx = NC * fxv, efy = NC * fyv, efz = NC * fzv;

        out[1 + j2] = qind;
        out[1 + NP + 3*j2 + 0] = al * efx;
        out[1 + NP + 3*j2 + 1] = al * efy;
        out[1 + NP + 3*j2 + 2] = al * efz;

        pot += qj * NC * (0.5f * a1v + a2v)
             - 0.5f * NC * ddv
             - 0.5f * ka * ephi * ephi
             - 0.5f * al * (efx * efx + efy * efy + efz * efz);
    }

    __shared__ float shpot[TPB];
    shpot[tid] = pot;
    __syncthreads();
#pragma unroll
    for (int ofs = TPB / 2; ofs > 0; ofs >>= 1) {
        if (tid < ofs) shpot[tid] += shpot[tid + ofs];
        __syncthreads();
    }
    if (tid == 0) out[0] = shpot[0];
}

extern "C" void kernel_launch(void* const* d_in, const int* in_sizes, int n_in,
                              void* d_out, int out_size)
{
    const float* q     = (const float*)d_in[0];
    const float* r     = (const float*)d_in[1];
    const float* u     = (const float*)d_in[4];
    const float* kappa = (const float*)d_in[5];
    const float* alpha = (const float*)d_in[6];
    float* out = (float*)d_out;

    // zero the accumulators + semaphore (graph-capturable memset nodes)
    void* acc_ptr = nullptr;
    void* sem_ptr = nullptr;
    cudaGetSymbolAddress(&acc_ptr, g_acc);
    cudaGetSymbolAddress(&sem_ptr, g_sem);
    cudaMemsetAsync(acc_ptr, 0, 6 * NP * sizeof(float));
    cudaMemsetAsync(sem_ptr, 0, sizeof(int));

    dim3 grid1(JBLK, SPLITS);
    ewald_pair_kernel<<<grid1, TPB>>>(q, r, u, kappa, alpha, out);
}

// round 10
// speedup vs baseline: 1.0938x; 1.0938x over previous
#include <cuda_runtime.h>

#define NP      3072
#define SPLITS  37
#define CHUNK   84              // 37*84 = 3108 >= 3072 (padded)
#define HC      (CHUNK / 2)     // 42 packed iterations
#define TPB     128
#define JBLK    (NP / TPB)      // 24 -> grid = 24*37 = 888 = 6*148 blocks (all resident)
#define TOTB    (JBLK * SPLITS) // 888
#define NGRP    (NP / 32)       // 96 j-groups
#define NTASK   (6 * NGRP)      // 576 stage-2 warp tasks

// constants (sigma = 1, A = 1/sqrt(2), A^2 = 1/2)
#define A_CONST 0.7071067811865476f
#define C1      0.7978845608028654f     // 2A/sqrt(pi) == 4A^3/sqrt(pi) since A^2=1/2
#define NC      14.399645f              // 90.4756 / (2*pi)
// Abramowitz-Stegun 7.1.26 erfc: erfc(x) = g*t*P(t), t=1/(1+p*x), |err|<=1.5e-7
#define P_AS  0.3275911f
#define PA    (P_AS * A_CONST)
#define AS1   0.254829592f
#define AS2  -0.284496736f
#define AS3   1.421413741f
#define AS4  -1.453152027f
#define AS5   1.061405429f
#define NL2E_HALF (-0.7213475204444817f)  // -0.5*log2(e)
#define RCUT2     20.25f                   // beyond this erf=1,g=0 to ~1e-4 rel
#define RINV_CUT  0.2222f                  // 1/sqrt(RCUT2)

typedef unsigned long long u64;

__device__ float g_part[SPLITS * 6 * NP];
__device__ float g_acc[6 * NP];
__device__ float g_potblk[JBLK];
__device__ int   g_ctr[4];     // [0]=bar1 [1]=bar2 [2]=epilogue sem (memset per replay)

__device__ __forceinline__ float rcp_fast(float x) {
    float y; asm("rcp.approx.f32 %0, %1;" : "=f"(y) : "f"(x)); return y;
}
__device__ __forceinline__ float ex2_fast(float x) {
    float y; asm("ex2.approx.f32 %0, %1;" : "=f"(y) : "f"(x)); return y;
}
__device__ __forceinline__ u64 pk(float lo, float hi) {
    u64 r; asm("mov.b64 %0, {%1, %2};" : "=l"(r) : "f"(lo), "f"(hi)); return r;
}
__device__ __forceinline__ void upk(u64 a, float& lo, float& hi) {
    asm("mov.b64 {%0, %1}, %2;" : "=f"(lo), "=f"(hi) : "l"(a));
}
__device__ __forceinline__ u64 fma2(u64 a, u64 b, u64 c) {
    u64 d; asm("fma.rn.f32x2 %0, %1, %2, %3;" : "=l"(d) : "l"(a), "l"(b), "l"(c)); return d;
}
__device__ __forceinline__ u64 mul2(u64 a, u64 b) {
    u64 d; asm("mul.rn.f32x2 %0, %1, %2;" : "=l"(d) : "l"(a), "l"(b)); return d;
}
__device__ __forceinline__ u64 add2(u64 a, u64 b) {
    u64 d; asm("add.rn.f32x2 %0, %1, %2;" : "=l"(d) : "l"(a), "l"(b)); return d;
}

__device__ __forceinline__ void grid_barrier(int which, int tid) {
    __threadfence();            // release my stores
    __syncthreads();
    if (tid == 0) {
        atomicAdd(&g_ctr[which], 1);
        volatile int* p = &g_ctr[which];
        while (*p < TOTB) __nanosleep(64);
    }
    __syncthreads();
    __threadfence();            // acquire others' stores
}

// scalar correction for one near pair: add (true - bare) terms; everything ~ g
__device__ __forceinline__ void corr_half(
    float dx, float dy, float dz, float qi,
    float ux, float uy, float uz, bool act,
    float& A1, float& A2,
    float& Hx, float& Hy, float& Hz,
    float& Wx, float& Wy, float& Wz,
    float& Gx, float& Gy, float& Gz)
{
    float t0 = dx * dx;
    t0 = fmaf(dy, dy, t0);
    const float d2 = fmaf(dz, dz, t0);
    const bool on = act && (d2 != 0.f) && (d2 < RCUT2);
    const float d2s  = fmaxf(d2, 1e-8f);
    const float rinv = rsqrtf(d2s);
    const float m    = on ? 1.f : 0.f;
    const float g    = ex2_fast(NL2E_HALF * d2s) * m;
    const float rn   = d2s * rinv;
    const float tt   = rcp_fast(fmaf(PA, rn, 1.f));
    const float poly = fmaf(fmaf(fmaf(fmaf(AS5, tt, AS4), tt, AS3), tt, AS2), tt, AS1);
    const float erfc = g * tt * poly;
    const float de   = -erfc * rinv;
    const float rr   = rinv * rinv;
    const float c1g  = C1 * g;
    const float ds1  = (de - c1g) * rr;
    const float uri  = fmaf(ux, dx, fmaf(uy, dy, uz * dz));
    const float ds2r = fmaf(3.f, ds1, -c1g) * (uri * rr);
    A1 = fmaf(qi, de, A1);
    A2 = fmaf(ds1, uri, A2);
    Hx = fmaf(ds2r, dx, Hx); Hy = fmaf(ds2r, dy, Hy); Hz = fmaf(ds2r, dz, Hz);
    const float qd = qi * ds1;
    Wx = fmaf(qd, dx, Wx); Wy = fmaf(qd, dy, Wy); Wz = fmaf(qd, dz, Wz);
    Gx = fmaf(ds1, ux, Gx); Gy = fmaf(ds1, uy, Gy); Gz = fmaf(ds1, uz, Gz);
}

__global__ __launch_bounds__(TPB, 6)
void ewald_fused_kernel(const float* __restrict__ q,
                        const float* __restrict__ r,
                        const float* __restrict__ u,
                        const float* __restrict__ kappa,
                        const float* __restrict__ alpha,
                        float* __restrict__ out)
{
    const int tid = threadIdx.x;
    const int j   = blockIdx.x * TPB + tid;
    const int s   = blockIdx.y;
    const int i0  = s * CHUNK;

    __shared__ ulonglong2 s_p0[HC];   // {-rx2, -ry2}
    __shared__ ulonglong2 s_p1[HC];   // {-rz2,   q2}
    __shared__ ulonglong2 s_p2[HC];   // { ux2,  uy2}
    __shared__ u64        s_p3[HC];   // { uz2 }

    for (int t = tid; t < HC; t += TPB) {
        const int ia = i0 + t;
        const int ib = ia + HC;
        float rxa, rya, rza, qa, uxa, uya, uza;
        float rxb, ryb, rzb, qb, uxb, uyb, uzb;
        if (ia < NP) {
            rxa = r[3*ia+0]; rya = r[3*ia+1]; rza = r[3*ia+2];
            qa = q[ia]; uxa = u[3*ia+0]; uya = u[3*ia+1]; uza = u[3*ia+2];
        } else { rxa=1e4f; rya=1e4f; rza=1e4f; qa=0.f; uxa=0.f; uya=0.f; uza=0.f; }
        if (ib < NP) {
            rxb = r[3*ib+0]; ryb = r[3*ib+1]; rzb = r[3*ib+2];
            qb = q[ib]; uxb = u[3*ib+0]; uyb = u[3*ib+1]; uzb = u[3*ib+2];
        } else { rxb=1e4f; ryb=1e4f; rzb=1e4f; qb=0.f; uxb=0.f; uyb=0.f; uzb=0.f; }
        s_p0[t] = make_ulonglong2(pk(-rxa, -rxb), pk(-rya, -ryb));
        s_p1[t] = make_ulonglong2(pk(-rza, -rzb), pk(qa, qb));
        s_p2[t] = make_ulonglong2(pk(uxa, uxb), pk(uya, uyb));
        s_p3[t] = pk(uza, uzb);
    }
    __syncthreads();

    const float rjx = r[3*j+0], rjy = r[3*j+1], rjz = r[3*j+2];
    const float ujx = u[3*j+0], ujy = u[3*j+1], ujz = u[3*j+2];

    const u64 rjx2 = pk(rjx, rjx), rjy2 = pk(rjy, rjy), rjz2 = pk(rjz, rjz);
    const u64 kThree = 0x4040000040400000ull;

    u64 a1 = 0, a2 = 0;
    u64 hx = 0, hy = 0, hz = 0;
    u64 wx = 0, wy = 0, wz = 0;
    u64 gx = 0, gy = 0, gz = 0;
    u64 mask = 0;

    // ---------------- Stage 1a: bare Coulomb (erf=1, g=0) for ALL pairs ----------------
#pragma unroll 6
    for (int t = 0; t < HC; ++t) {
        const ulonglong2 p0 = s_p0[t];
        const ulonglong2 p1 = s_p1[t];
        const ulonglong2 p2 = s_p2[t];
        const u64 uz2 = s_p3[t];

        const u64 dx = add2(rjx2, p0.x);
        const u64 dy = add2(rjy2, p0.y);
        const u64 dz = add2(rjz2, p1.x);
        u64 d2 = mul2(dx, dx);
        d2 = fma2(dy, dy, d2);
        d2 = fma2(dz, dz, d2);

        float d2l, d2h; upk(d2, d2l, d2h);
        float rl = rsqrtf(d2l), rh = rsqrtf(d2h);
        rl = (d2l == 0.f) ? 0.f : rl;
        rh = (d2h == 0.f) ? 0.f : rh;
        const bool near = fmaxf(rl, rh) > RINV_CUT;
        mask |= ((u64)near) << t;

        const u64 rinv = pk(rl, rh);
        const u64 rr   = mul2(rinv, rinv);
        const u64 s1   = mul2(rinv, rr);

        a1 = fma2(p1.y, rinv, a1);

        u64 uri = mul2(p2.x, dx);
        uri = fma2(p2.y, dy, uri);
        uri = fma2(uz2, dz, uri);
        a2 = fma2(s1, uri, a2);

        const u64 v   = mul2(uri, rr);
        const u64 v3  = mul2(v, kThree);
        const u64 s2r = mul2(s1, v3);

        hx = fma2(s2r, dx, hx);
        hy = fma2(s2r, dy, hy);
        hz = fma2(s2r, dz, hz);
        const u64 qs1 = mul2(p1.y, s1);
        wx = fma2(qs1, dx, wx);
        wy = fma2(qs1, dy, wy);
        wz = fma2(qs1, dz, wz);
        gx = fma2(s1, p2.x, gx);
        gy = fma2(s1, p2.y, gy);
        gz = fma2(s1, uz2, gz);
    }

    float l, h;
    upk(a1, l, h); float A1 = l + h;
    upk(a2, l, h); float A2 = l + h;
    upk(hx, l, h); float Hx = l + h;
    upk(hy, l, h); float Hy = l + h;
    upk(hz, l, h); float Hz = l + h;
    upk(wx, l, h); float Wx = l + h;
    upk(wy, l, h); float Wy = l + h;
    upk(wz, l, h); float Wz = l + h;
    upk(gx, l, h); float Gx = l + h;
    upk(gy, l, h); float Gy = l + h;
    upk(gz, l, h); float Gz = l + h;

    // ---------------- Stage 1b: sparse erf/gauss corrections for near pairs ----------------
    unsigned mlo = (unsigned)mask;
    unsigned mhi = (unsigned)(mask >> 32);
    while (__any_sync(0xFFFFFFFFu, mlo | mhi)) {
        const bool act = (mlo | mhi) != 0u;
        int t = 0;
        if (mlo) { t = __ffs(mlo) - 1;  mlo &= mlo - 1u; }
        else if (mhi) { t = __ffs(mhi) + 31; mhi &= mhi - 1u; }

        const ulonglong2 p0 = s_p0[t];
        const ulonglong2 p1 = s_p1[t];
        const ulonglong2 p2 = s_p2[t];
        const u64 uz2 = s_p3[t];
        float nrxl, nrxh, nryl, nryh, nrzl, nrzh, ql, qh;
        float uxl, uxh, uyl, uyh, uzl, uzh;
        upk(p0.x, nrxl, nrxh); upk(p0.y, nryl, nryh);
        upk(p1.x, nrzl, nrzh); upk(p1.y, ql, qh);
        upk(p2.x, uxl, uxh);   upk(p2.y, uyl, uyh);
        upk(uz2, uzl, uzh);

        corr_half(rjx + nrxl, rjy + nryl, rjz + nrzl, ql, uxl, uyl, uzl, act,
                  A1, A2, Hx, Hy, Hz, Wx, Wy, Wz, Gx, Gy, Gz);
        corr_half(rjx + nrxh, rjy + nryh, rjz + nrzh, qh, uxh, uyh, uzh, act,
                  A1, A2, Hx, Hy, Hz, Wx, Wy, Wz, Gx, Gy, Gz);
    }

    const float Mx = Hx - Gx, My = Hy - Gy, Mz = Hz - Gz;
    const float fx = Wx + Mx, fy = Wy + My, fz = Wz + Mz;
    const float dd = ujx * Mx + ujy * My + ujz * Mz;

    {
        float* p = g_part + (size_t)s * 6 * NP;
        p[0*NP + j] = A1;
        p[1*NP + j] = A2;
        p[2*NP + j] = fx;
        p[3*NP + j] = fy;
        p[4*NP + j] = fz;
        p[5*NP + j] = dd;
    }

    // ---------------- Barrier 1: all partials visible ----------------
    grid_barrier(0, tid);

    // ---------------- Stage 2: 576 warps sum 37 splits each (L2-hot, deterministic) ----------------
    {
        const int wid  = tid >> 5;
        const int lane = tid & 31;
        const int W = (blockIdx.y * JBLK + blockIdx.x) * 4 + wid;
        if (W < NTASK) {
            const int c   = W / NGRP;
            const int grp = W % NGRP;
            const int jj  = grp * 32 + lane;
            const float* bp = g_part + (size_t)c * NP + jj;
            float c0 = 0.f, c1v = 0.f, c2 = 0.f, c3 = 0.f;
#pragma unroll
            for (int k = 0; k < 36; k += 4) {
                c0 += bp[(size_t)(k    ) * 6 * NP];
                c1v += bp[(size_t)(k + 1) * 6 * NP];
                c2 += bp[(size_t)(k + 2) * 6 * NP];
                c3 += bp[(size_t)(k + 3) * 6 * NP];
            }
            g_acc[c * NP + jj] = ((c0 + c1v) + (c2 + c3)) + bp[(size_t)36 * 6 * NP];
        }
    }

    // ---------------- Barrier 2: g_acc visible ----------------
    grid_barrier(1, tid);

    if (blockIdx.y != 0) return;

    // ---------------- Stage 3: epilogue, 24 blocks, j == this block's own j ----------------
    {
        const float a1v = g_acc[0*NP + j];
        const float a2v = g_acc[1*NP + j];
        const float fxv = g_acc[2*NP + j];
        const float fyv = g_acc[3*NP + j];
        const float fzv = g_acc[4*NP + j];
        const float ddv = g_acc[5*NP + j];

        const float ka = kappa[j];
        const float al = alpha[j];
        const float qj = q[j];

        const float ephi = NC * (a1v + a2v);
        const float qind = -ka * ephi;
        const float efx = NC * fxv, efy = NC * fyv, efz = NC * fzv;

        out[1 + j] = qind;
        out[1 + NP + 3*j + 0] = al * efx;
        out[1 + NP + 3*j + 1] = al * efy;
        out[1 + NP + 3*j + 2] = al * efz;

        float potj = qj * NC * (0.5f * a1v + a2v)
                   - 0.5f * NC * ddv
                   - 0.5f * ka * ephi * ephi
                   - 0.5f * al * (efx * efx + efy * efy + efz * efz);

        __shared__ float shpot[TPB];
        shpot[tid] = potj;
        __syncthreads();
#pragma unroll
        for (int ofs = TPB / 2; ofs > 0; ofs >>= 1) {
            if (tid < ofs) shpot[tid] += shpot[tid + ofs];
            __syncthreads();
        }

        __shared__ bool lastblk;
        if (tid == 0) {
            g_potblk[blockIdx.x] = shpot[0];
            __threadfence();
            const int old = atomicAdd(&g_ctr[2], 1);
            lastblk = (old == JBLK - 1);
        }
        __syncthreads();

        if (lastblk && tid < 32) {
            __threadfence();
            float v = (tid < JBLK) ? g_potblk[tid] : 0.f;
#pragma unroll
            for (int ofs = 16; ofs > 0; ofs >>= 1)
                v += __shfl_down_sync(0xFFFFFFFFu, v, ofs);
            if (tid == 0) out[0] = v;
        }
    }
}

extern "C" void kernel_launch(void* const* d_in, const int* in_sizes, int n_in,
                              void* d_out, int out_size)
{
    const float* q     = (const float*)d_in[0];
    const float* r     = (const float*)d_in[1];
    const float* u     = (const float*)d_in[4];
    const float* kappa = (const float*)d_in[5];
    const float* alpha = (const float*)d_in[6];
    float* out = (float*)d_out;

    void* ctr_ptr = nullptr;
    cudaGetSymbolAddress(&ctr_ptr, g_ctr);
    cudaMemsetAsync(ctr_ptr, 0, 4 * sizeof(int));

    dim3 grid(JBLK, SPLITS);
    ewald_fused_kernel<<<grid, TPB>>>(q, r, u, kappa, alpha, out);
}

// round 11
// speedup vs baseline: 1.1337x; 1.0365x over previous
#include <cuda_runtime.h>

#define NP      3072
#define SPLITS  37
#define CHUNK   84              // 37*84 = 3108 >= 3072 (padded)
#define HC      (CHUNK / 2)     // 42 packed iterations
#define TPB     128
#define JBLK    (NP / TPB)      // 24 columns -> grid = 24*37 = 888 = 6*148 blocks
#define NTASK   192             // 6 comps * 32 float4-groups per column

// constants (sigma = 1, A = 1/sqrt(2), A^2 = 1/2)
#define A_CONST 0.7071067811865476f
#define C1      0.7978845608028654f     // 2A/sqrt(pi) == 4A^3/sqrt(pi) since A^2=1/2
#define NC      14.399645f              // 90.4756 / (2*pi)
// Abramowitz-Stegun 7.1.26 erfc: erfc(x) = g*t*P(t), t=1/(1+p*x), |err|<=1.5e-7
#define P_AS  0.3275911f
#define PA    (P_AS * A_CONST)
#define AS1   0.254829592f
#define AS2  -0.284496736f
#define AS3   1.421413741f
#define AS4  -1.453152027f
#define AS5   1.061405429f
#define NL2E_HALF (-0.7213475204444817f)  // -0.5*log2(e)
#define RCUT2     20.25f                   // beyond this erf=1,g=0 to ~1e-4 rel
#define RINV_CUT  0.2222f                  // 1/sqrt(RCUT2)

typedef unsigned long long u64;

__device__ float g_part[SPLITS * 6 * NP];
__device__ float g_potblk[JBLK];
__device__ int   g_colctr[JBLK];   // per-column arrival counters (memset per replay)
__device__ int   g_finctr;         // final pot semaphore       (memset per replay)

__device__ __forceinline__ float rcp_fast(float x) {
    float y; asm("rcp.approx.f32 %0, %1;" : "=f"(y) : "f"(x)); return y;
}
__device__ __forceinline__ float ex2_fast(float x) {
    float y; asm("ex2.approx.f32 %0, %1;" : "=f"(y) : "f"(x)); return y;
}
__device__ __forceinline__ u64 pk(float lo, float hi) {
    u64 r; asm("mov.b64 %0, {%1, %2};" : "=l"(r) : "f"(lo), "f"(hi)); return r;
}
__device__ __forceinline__ void upk(u64 a, float& lo, float& hi) {
    asm("mov.b64 {%0, %1}, %2;" : "=f"(lo), "=f"(hi) : "l"(a));
}
__device__ __forceinline__ u64 fma2(u64 a, u64 b, u64 c) {
    u64 d; asm("fma.rn.f32x2 %0, %1, %2, %3;" : "=l"(d) : "l"(a), "l"(b), "l"(c)); return d;
}
__device__ __forceinline__ u64 mul2(u64 a, u64 b) {
    u64 d; asm("mul.rn.f32x2 %0, %1, %2;" : "=l"(d) : "l"(a), "l"(b)); return d;
}
__device__ __forceinline__ u64 add2(u64 a, u64 b) {
    u64 d; asm("add.rn.f32x2 %0, %1, %2;" : "=l"(d) : "l"(a), "l"(b)); return d;
}

// scalar correction for one near pair: add (true - bare) terms; everything ~ g
__device__ __forceinline__ void corr_half(
    float dx, float dy, float dz, float qi,
    float ux, float uy, float uz, bool act,
    float& A1, float& A2,
    float& Hx, float& Hy, float& Hz,
    float& Wx, float& Wy, float& Wz,
    float& Gx, float& Gy, float& Gz)
{
    float t0 = dx * dx;
    t0 = fmaf(dy, dy, t0);
    const float d2 = fmaf(dz, dz, t0);
    const bool on = act && (d2 != 0.f) && (d2 < RCUT2);
    const float d2s  = fmaxf(d2, 1e-8f);
    const float rinv = rsqrtf(d2s);
    const float m    = on ? 1.f : 0.f;
    const float g    = ex2_fast(NL2E_HALF * d2s) * m;
    const float rn   = d2s * rinv;
    const float tt   = rcp_fast(fmaf(PA, rn, 1.f));
    const float poly = fmaf(fmaf(fmaf(fmaf(AS5, tt, AS4), tt, AS3), tt, AS2), tt, AS1);
    const float erfc = g * tt * poly;
    const float de   = -erfc * rinv;
    const float rr   = rinv * rinv;
    const float c1g  = C1 * g;
    const float ds1  = (de - c1g) * rr;
    const float uri  = fmaf(ux, dx, fmaf(uy, dy, uz * dz));
    const float ds2r = fmaf(3.f, ds1, -c1g) * (uri * rr);
    A1 = fmaf(qi, de, A1);
    A2 = fmaf(ds1, uri, A2);
    Hx = fmaf(ds2r, dx, Hx); Hy = fmaf(ds2r, dy, Hy); Hz = fmaf(ds2r, dz, Hz);
    const float qd = qi * ds1;
    Wx = fmaf(qd, dx, Wx); Wy = fmaf(qd, dy, Wy); Wz = fmaf(qd, dz, Wz);
    Gx = fmaf(ds1, ux, Gx); Gy = fmaf(ds1, uy, Gy); Gz = fmaf(ds1, uz, Gz);
}

__global__ __launch_bounds__(TPB, 6)
void ewald_pair_kernel(const float* __restrict__ q,
                       const float* __restrict__ r,
                       const float* __restrict__ u,
                       const float* __restrict__ kappa,
                       const float* __restrict__ alpha,
                       float* __restrict__ out)
{
    const int tid = threadIdx.x;
    const int j   = blockIdx.x * TPB + tid;
    const int s   = blockIdx.y;
    const int i0  = s * CHUNK;

    __shared__ ulonglong2 s_p0[HC];   // {-rx2, -ry2}
    __shared__ ulonglong2 s_p1[HC];   // {-rz2,   q2}
    __shared__ ulonglong2 s_p2[HC];   // { ux2,  uy2}
    __shared__ u64        s_p3[HC];   // { uz2 }

    for (int t = tid; t < HC; t += TPB) {
        const int ia = i0 + t;
        const int ib = ia + HC;
        float rxa, rya, rza, qa, uxa, uya, uza;
        float rxb, ryb, rzb, qb, uxb, uyb, uzb;
        if (ia < NP) {
            rxa = r[3*ia+0]; rya = r[3*ia+1]; rza = r[3*ia+2];
            qa = q[ia]; uxa = u[3*ia+0]; uya = u[3*ia+1]; uza = u[3*ia+2];
        } else { rxa=1e4f; rya=1e4f; rza=1e4f; qa=0.f; uxa=0.f; uya=0.f; uza=0.f; }
        if (ib < NP) {
            rxb = r[3*ib+0]; ryb = r[3*ib+1]; rzb = r[3*ib+2];
            qb = q[ib]; uxb = u[3*ib+0]; uyb = u[3*ib+1]; uzb = u[3*ib+2];
        } else { rxb=1e4f; ryb=1e4f; rzb=1e4f; qb=0.f; uxb=0.f; uyb=0.f; uzb=0.f; }
        s_p0[t] = make_ulonglong2(pk(-rxa, -rxb), pk(-rya, -ryb));
        s_p1[t] = make_ulonglong2(pk(-rza, -rzb), pk(qa, qb));
        s_p2[t] = make_ulonglong2(pk(uxa, uxb), pk(uya, uyb));
        s_p3[t] = pk(uza, uzb);
    }
    __syncthreads();

    const float rjx = r[3*j+0], rjy = r[3*j+1], rjz = r[3*j+2];
    const float ujx = u[3*j+0], ujy = u[3*j+1], ujz = u[3*j+2];

    const u64 rjx2 = pk(rjx, rjx), rjy2 = pk(rjy, rjy), rjz2 = pk(rjz, rjz);
    const u64 kThree = 0x4040000040400000ull;

    u64 a1 = 0, a2 = 0;
    u64 hx = 0, hy = 0, hz = 0;
    u64 wx = 0, wy = 0, wz = 0;
    u64 gx = 0, gy = 0, gz = 0;
    u64 mask = 0;

    // ---------------- Pass A: bare Coulomb (erf=1, g=0) for ALL pairs ----------------
#pragma unroll 6
    for (int t = 0; t < HC; ++t) {
        const ulonglong2 p0 = s_p0[t];
        const ulonglong2 p1 = s_p1[t];
        const ulonglong2 p2 = s_p2[t];
        const u64 uz2 = s_p3[t];

        const u64 dx = add2(rjx2, p0.x);
        const u64 dy = add2(rjy2, p0.y);
        const u64 dz = add2(rjz2, p1.x);
        u64 d2 = mul2(dx, dx);
        d2 = fma2(dy, dy, d2);
        d2 = fma2(dz, dz, d2);

        float d2l, d2h; upk(d2, d2l, d2h);
        float rl = rsqrtf(d2l), rh = rsqrtf(d2h);
        rl = (d2l == 0.f) ? 0.f : rl;
        rh = (d2h == 0.f) ? 0.f : rh;
        const bool near = fmaxf(rl, rh) > RINV_CUT;
        mask |= ((u64)near) << t;

        const u64 rinv = pk(rl, rh);
        const u64 rr   = mul2(rinv, rinv);
        const u64 s1   = mul2(rinv, rr);

        a1 = fma2(p1.y, rinv, a1);

        u64 uri = mul2(p2.x, dx);
        uri = fma2(p2.y, dy, uri);
        uri = fma2(uz2, dz, uri);
        a2 = fma2(s1, uri, a2);

        const u64 v   = mul2(uri, rr);
        const u64 v3  = mul2(v, kThree);
        const u64 s2r = mul2(s1, v3);

        hx = fma2(s2r, dx, hx);
        hy = fma2(s2r, dy, hy);
        hz = fma2(s2r, dz, hz);
        const u64 qs1 = mul2(p1.y, s1);
        wx = fma2(qs1, dx, wx);
        wy = fma2(qs1, dy, wy);
        wz = fma2(qs1, dz, wz);
        gx = fma2(s1, p2.x, gx);
        gy = fma2(s1, p2.y, gy);
        gz = fma2(s1, uz2, gz);
    }

    float l, h;
    upk(a1, l, h); float A1 = l + h;
    upk(a2, l, h); float A2 = l + h;
    upk(hx, l, h); float Hx = l + h;
    upk(hy, l, h); float Hy = l + h;
    upk(hz, l, h); float Hz = l + h;
    upk(wx, l, h); float Wx = l + h;
    upk(wy, l, h); float Wy = l + h;
    upk(wz, l, h); float Wz = l + h;
    upk(gx, l, h); float Gx = l + h;
    upk(gy, l, h); float Gy = l + h;
    upk(gz, l, h); float Gz = l + h;

    // ---------------- Pass B: sparse erf/gauss corrections for near pairs ----------------
    unsigned mlo = (unsigned)mask;
    unsigned mhi = (unsigned)(mask >> 32);
    while (__any_sync(0xFFFFFFFFu, mlo | mhi)) {
        const bool act = (mlo | mhi) != 0u;
        int t = 0;
        if (mlo) { t = __ffs(mlo) - 1;  mlo &= mlo - 1u; }
        else if (mhi) { t = __ffs(mhi) + 31; mhi &= mhi - 1u; }

        const ulonglong2 p0 = s_p0[t];
        const ulonglong2 p1 = s_p1[t];
        const ulonglong2 p2 = s_p2[t];
        const u64 uz2 = s_p3[t];
        float nrxl, nrxh, nryl, nryh, nrzl, nrzh, ql, qh;
        float uxl, uxh, uyl, uyh, uzl, uzh;
        upk(p0.x, nrxl, nrxh); upk(p0.y, nryl, nryh);
        upk(p1.x, nrzl, nrzh); upk(p1.y, ql, qh);
        upk(p2.x, uxl, uxh);   upk(p2.y, uyl, uyh);
        upk(uz2, uzl, uzh);

        corr_half(rjx + nrxl, rjy + nryl, rjz + nrzl, ql, uxl, uyl, uzl, act,
                  A1, A2, Hx, Hy, Hz, Wx, Wy, Wz, Gx, Gy, Gz);
        corr_half(rjx + nrxh, rjy + nryh, rjz + nrzh, qh, uxh, uyh, uzh, act,
                  A1, A2, Hx, Hy, Hz, Wx, Wy, Wz, Gx, Gy, Gz);
    }

    const float Mx = Hx - Gx, My = Hy - Gy, Mz = Hz - Gz;
    const float fx = Wx + Mx, fy = Wy + My, fz = Wz + Mz;
    const float dd = ujx * Mx + ujy * My + ujz * Mz;

    {
        float* p = g_part + (size_t)s * 6 * NP;
        p[0*NP + j] = A1;
        p[1*NP + j] = A2;
        p[2*NP + j] = fx;
        p[3*NP + j] = fy;
        p[4*NP + j] = fz;
        p[5*NP + j] = dd;
    }

    // ---------------- per-column last-block reduction (no grid barrier) ----------------
    __threadfence();                      // release this block's partials
    __syncthreads();
    __shared__ bool lastcol;
    if (tid == 0) {
        const int old = atomicAdd(&g_colctr[blockIdx.x], 1);
        lastcol = (old == SPLITS - 1);
    }
    __syncthreads();
    if (!lastcol) return;
    __threadfence();                      // acquire all 37 blocks' partials (L2-hot)

    // sum this column's 37 partials: 192 float4-tasks over 128 threads
    __shared__ float shacc[6][TPB];
    for (int task = tid; task < NTASK; task += TPB) {
        const int c  = task >> 5;         // 0..5
        const int g4 = task & 31;         // 0..31
        const float4* bp = (const float4*)(g_part + (size_t)c * NP
                                           + blockIdx.x * TPB + g4 * 4);
        float4 acc = make_float4(0.f, 0.f, 0.f, 0.f);
#pragma unroll
        for (int s2 = 0; s2 < SPLITS; ++s2) {
            const float4 v = bp[s2 * (6 * NP / 4)];
            acc.x += v.x; acc.y += v.y; acc.z += v.z; acc.w += v.w;
        }
        shacc[c][g4 * 4 + 0] = acc.x;
        shacc[c][g4 * 4 + 1] = acc.y;
        shacc[c][g4 * 4 + 2] = acc.z;
        shacc[c][g4 * 4 + 3] = acc.w;
    }
    __syncthreads();

    // epilogue for this block's own j
    {
        const float a1v = shacc[0][tid];
        const float a2v = shacc[1][tid];
        const float fxv = shacc[2][tid];
        const float fyv = shacc[3][tid];
        const float fzv = shacc[4][tid];
        const float ddv = shacc[5][tid];

        const float ka = kappa[j];
        const float al = alpha[j];
        const float qj = q[j];

        const float ephi = NC * (a1v + a2v);
        const float qind = -ka * ephi;
        const float efx = NC * fxv, efy = NC * fyv, efz = NC * fzv;

        out[1 + j] = qind;
        out[1 + NP + 3*j + 0] = al * efx;
        out[1 + NP + 3*j + 1] = al * efy;
        out[1 + NP + 3*j + 2] = al * efz;

        float potj = qj * NC * (0.5f * a1v + a2v)
                   - 0.5f * NC * ddv
                   - 0.5f * ka * ephi * ephi
                   - 0.5f * al * (efx * efx + efy * efy + efz * efz);

        __shared__ float shpot[TPB];
        shpot[tid] = potj;
        __syncthreads();
#pragma unroll
        for (int ofs = TPB / 2; ofs > 0; ofs >>= 1) {
            if (tid < ofs) shpot[tid] += shpot[tid + ofs];
            __syncthreads();
        }

        __shared__ bool lastfin;
        if (tid == 0) {
            g_potblk[blockIdx.x] = shpot[0];
            __threadfence();
            const int old = atomicAdd(&g_finctr, 1);
            lastfin = (old == JBLK - 1);
        }
        __syncthreads();

        if (lastfin && tid < 32) {
            __threadfence();
            float v = (tid < JBLK) ? g_potblk[tid] : 0.f;
#pragma unroll
            for (int ofs = 16; ofs > 0; ofs >>= 1)
                v += __shfl_down_sync(0xFFFFFFFFu, v, ofs);
            if (tid == 0) out[0] = v;
        }
    }
}

extern "C" void kernel_launch(void* const* d_in, const int* in_sizes, int n_in,
                              void* d_out, int out_size)
{
    const float* q     = (const float*)d_in[0];
    const float* r     = (const float*)d_in[1];
    const float* u     = (const float*)d_in[4];
    const float* kappa = (const float*)d_in[5];
    const float* alpha = (const float*)d_in[6];
    float* out = (float*)d_out;

    // zero the per-column + final counters (tiny, graph-capturable memset nodes)
    void* colp = nullptr;
    void* finp = nullptr;
    cudaGetSymbolAddress(&colp, g_colctr);
    cudaGetSymbolAddress(&finp, g_finctr);
    cudaMemsetAsync(colp, 0, JBLK * sizeof(int));
    cudaMemsetAsync(finp, 0, sizeof(int));

    dim3 grid(JBLK, SPLITS);
    ewald_pair_kernel<<<grid, TPB>>>(q, r, u, kappa, alpha, out);
}

// round 12
// speedup vs baseline: 1.4093x; 1.2431x over previous
#include <cuda_runtime.h>

#define NP      3072
#define SPLITS  48
#define CHUNK   64              // 48*64 = 3072 exactly, no padding
#define HC      (CHUNK / 2)     // 32 packed iterations -> u32 near-mask
#define TPB     128
#define JBLK    (NP / TPB)      // 24 -> grid = 24*48 = 1152 blocks (~7.8/SM at occ 8)

#define RJ      32              // j per reduce block
#define RBLK    (NP / RJ)       // 96 reduce blocks
#define NSL     4               // split-slices per (c,j) -> 12 loads each, exact
#define TPB2    (RJ * 6 * NSL)  // 768 threads

// constants (sigma = 1, A = 1/sqrt(2), A^2 = 1/2)
#define A_CONST 0.7071067811865476f
#define C1      0.7978845608028654f     // 2A/sqrt(pi) == 4A^3/sqrt(pi) since A^2=1/2
#define NC      14.399645f              // 90.4756 / (2*pi)
// Abramowitz-Stegun 7.1.26 erfc: erfc(x) = g*t*P(t), t=1/(1+p*x), |err|<=1.5e-7
#define P_AS  0.3275911f
#define PA    (P_AS * A_CONST)
#define AS1   0.254829592f
#define AS2  -0.284496736f
#define AS3   1.421413741f
#define AS4  -1.453152027f
#define AS5   1.061405429f
#define NL2E_HALF (-0.7213475204444817f)  // -0.5*log2(e)
#define RCUT2     20.25f                   // beyond this erf=1,g=0 to ~1e-4 rel
#define RINV_CUT  0.2222f                  // 1/sqrt(RCUT2)

typedef unsigned long long u64;

__device__ float g_part[SPLITS * 6 * NP];
__device__ float g_potblk[RBLK];
__device__ int   g_sem;          // reset in-kernel after use

__device__ __forceinline__ float rcp_fast(float x) {
    float y; asm("rcp.approx.f32 %0, %1;" : "=f"(y) : "f"(x)); return y;
}
__device__ __forceinline__ float ex2_fast(float x) {
    float y; asm("ex2.approx.f32 %0, %1;" : "=f"(y) : "f"(x)); return y;
}
__device__ __forceinline__ u64 pk(float lo, float hi) {
    u64 r; asm("mov.b64 %0, {%1, %2};" : "=l"(r) : "f"(lo), "f"(hi)); return r;
}
__device__ __forceinline__ void upk(u64 a, float& lo, float& hi) {
    asm("mov.b64 {%0, %1}, %2;" : "=f"(lo), "=f"(hi) : "l"(a));
}
__device__ __forceinline__ u64 fma2(u64 a, u64 b, u64 c) {
    u64 d; asm("fma.rn.f32x2 %0, %1, %2, %3;" : "=l"(d) : "l"(a), "l"(b), "l"(c)); return d;
}
__device__ __forceinline__ u64 mul2(u64 a, u64 b) {
    u64 d; asm("mul.rn.f32x2 %0, %1, %2;" : "=l"(d) : "l"(a), "l"(b)); return d;
}
__device__ __forceinline__ u64 add2(u64 a, u64 b) {
    u64 d; asm("add.rn.f32x2 %0, %1, %2;" : "=l"(d) : "l"(a), "l"(b)); return d;
}

// scalar correction for one near pair: add (true - bare) terms; everything ~ g
__device__ __forceinline__ void corr_half(
    float dx, float dy, float dz, float qi,
    float ux, float uy, float uz, bool act,
    float& A1, float& A2,
    float& Hx, float& Hy, float& Hz,
    float& Wx, float& Wy, float& Wz,
    float& Gx, float& Gy, float& Gz)
{
    float t0 = dx * dx;
    t0 = fmaf(dy, dy, t0);
    const float d2 = fmaf(dz, dz, t0);
    const bool on = act && (d2 != 0.f) && (d2 < RCUT2);
    const float d2s  = fmaxf(d2, 1e-8f);
    const float rinv = rsqrtf(d2s);
    const float m    = on ? 1.f : 0.f;
    const float g    = ex2_fast(NL2E_HALF * d2s) * m;
    const float rn   = d2s * rinv;
    const float tt   = rcp_fast(fmaf(PA, rn, 1.f));
    const float poly = fmaf(fmaf(fmaf(fmaf(AS5, tt, AS4), tt, AS3), tt, AS2), tt, AS1);
    const float erfc = g * tt * poly;
    const float de   = -erfc * rinv;
    const float rr   = rinv * rinv;
    const float c1g  = C1 * g;
    const float ds1  = (de - c1g) * rr;
    const float uri  = fmaf(ux, dx, fmaf(uy, dy, uz * dz));
    const float ds2r = fmaf(3.f, ds1, -c1g) * (uri * rr);
    A1 = fmaf(qi, de, A1);
    A2 = fmaf(ds1, uri, A2);
    Hx = fmaf(ds2r, dx, Hx); Hy = fmaf(ds2r, dy, Hy); Hz = fmaf(ds2r, dz, Hz);
    const float qd = qi * ds1;
    Wx = fmaf(qd, dx, Wx); Wy = fmaf(qd, dy, Wy); Wz = fmaf(qd, dz, Wz);
    Gx = fmaf(ds1, ux, Gx); Gy = fmaf(ds1, uy, Gy); Gz = fmaf(ds1, uz, Gz);
}

__global__ __launch_bounds__(TPB, 8)
void ewald_pair_kernel(const float* __restrict__ q,
                       const float* __restrict__ r,
                       const float* __restrict__ u)
{
    const int tid = threadIdx.x;
    const int j   = blockIdx.x * TPB + tid;
    const int s   = blockIdx.y;
    const int i0  = s * CHUNK;

    __shared__ ulonglong2 s_p0[HC];   // {-rx2, -ry2}
    __shared__ ulonglong2 s_p1[HC];   // {-rz2,   q2}
    __shared__ ulonglong2 s_p2[HC];   // { ux2,  uy2}
    __shared__ u64        s_p3[HC];   // { uz2 }

    if (tid < HC) {
        const int ia = i0 + tid;
        const int ib = ia + HC;
        const float rxa = r[3*ia+0], rya = r[3*ia+1], rza = r[3*ia+2];
        const float rxb = r[3*ib+0], ryb = r[3*ib+1], rzb = r[3*ib+2];
        s_p0[tid] = make_ulonglong2(pk(-rxa, -rxb), pk(-rya, -ryb));
        s_p1[tid] = make_ulonglong2(pk(-rza, -rzb), pk(q[ia], q[ib]));
        s_p2[tid] = make_ulonglong2(pk(u[3*ia+0], u[3*ib+0]), pk(u[3*ia+1], u[3*ib+1]));
        s_p3[tid] = pk(u[3*ia+2], u[3*ib+2]);
    }
    __syncthreads();

    const float rjx = r[3*j+0], rjy = r[3*j+1], rjz = r[3*j+2];
    const float ujx = u[3*j+0], ujy = u[3*j+1], ujz = u[3*j+2];

    const u64 rjx2 = pk(rjx, rjx), rjy2 = pk(rjy, rjy), rjz2 = pk(rjz, rjz);
    const u64 kThree = 0x4040000040400000ull;

    u64 a1 = 0, a2 = 0;
    u64 hx = 0, hy = 0, hz = 0;
    u64 wx = 0, wy = 0, wz = 0;
    u64 gx = 0, gy = 0, gz = 0;
    unsigned mask = 0;

    // ---------------- Pass A: bare Coulomb (erf=1, g=0) for ALL pairs ----------------
#pragma unroll 4
    for (int t = 0; t < HC; ++t) {
        const ulonglong2 p0 = s_p0[t];
        const ulonglong2 p1 = s_p1[t];
        const ulonglong2 p2 = s_p2[t];
        const u64 uz2 = s_p3[t];

        const u64 dx = add2(rjx2, p0.x);
        const u64 dy = add2(rjy2, p0.y);
        const u64 dz = add2(rjz2, p1.x);
        u64 d2 = mul2(dx, dx);
        d2 = fma2(dy, dy, d2);
        d2 = fma2(dz, dz, d2);

        float d2l, d2h; upk(d2, d2l, d2h);
        float rl = rsqrtf(d2l), rh = rsqrtf(d2h);
        rl = (d2l == 0.f) ? 0.f : rl;          // self pair -> contributes exactly 0
        rh = (d2h == 0.f) ? 0.f : rh;
        const bool near = fmaxf(rl, rh) > RINV_CUT;
        mask |= ((unsigned)near) << t;

        const u64 rinv = pk(rl, rh);
        const u64 rr   = mul2(rinv, rinv);
        const u64 s1   = mul2(rinv, rr);

        a1 = fma2(p1.y, rinv, a1);

        u64 uri = mul2(p2.x, dx);
        uri = fma2(p2.y, dy, uri);
        uri = fma2(uz2, dz, uri);
        a2 = fma2(s1, uri, a2);

        const u64 v   = mul2(uri, rr);
        const u64 v3  = mul2(v, kThree);
        const u64 s2r = mul2(s1, v3);

        hx = fma2(s2r, dx, hx);
        hy = fma2(s2r, dy, hy);
        hz = fma2(s2r, dz, hz);
        const u64 qs1 = mul2(p1.y, s1);
        wx = fma2(qs1, dx, wx);
        wy = fma2(qs1, dy, wy);
        wz = fma2(qs1, dz, wz);
        gx = fma2(s1, p2.x, gx);
        gy = fma2(s1, p2.y, gy);
        gz = fma2(s1, uz2, gz);
    }

    float l, h;
    upk(a1, l, h); float A1 = l + h;
    upk(a2, l, h); float A2 = l + h;
    upk(hx, l, h); float Hx = l + h;
    upk(hy, l, h); float Hy = l + h;
    upk(hz, l, h); float Hz = l + h;
    upk(wx, l, h); float Wx = l + h;
    upk(wy, l, h); float Wy = l + h;
    upk(wz, l, h); float Wz = l + h;
    upk(gx, l, h); float Gx = l + h;
    upk(gy, l, h); float Gy = l + h;
    upk(gz, l, h); float Gz = l + h;

    // ---------------- Pass B: sparse erf/gauss corrections for near pairs ----------------
    while (__any_sync(0xFFFFFFFFu, mask)) {
        const bool act = mask != 0u;
        int t = 0;
        if (mask) { t = __ffs(mask) - 1; mask &= mask - 1u; }

        const ulonglong2 p0 = s_p0[t];
        const ulonglong2 p1 = s_p1[t];
        const ulonglong2 p2 = s_p2[t];
        const u64 uz2 = s_p3[t];
        float nrxl, nrxh, nryl, nryh, nrzl, nrzh, ql, qh;
        float uxl, uxh, uyl, uyh, uzl, uzh;
        upk(p0.x, nrxl, nrxh); upk(p0.y, nryl, nryh);
        upk(p1.x, nrzl, nrzh); upk(p1.y, ql, qh);
        upk(p2.x, uxl, uxh);   upk(p2.y, uyl, uyh);
        upk(uz2, uzl, uzh);

        corr_half(rjx + nrxl, rjy + nryl, rjz + nrzl, ql, uxl, uyl, uzl, act,
                  A1, A2, Hx, Hy, Hz, Wx, Wy, Wz, Gx, Gy, Gz);
        corr_half(rjx + nrxh, rjy + nryh, rjz + nrzh, qh, uxh, uyh, uzh, act,
                  A1, A2, Hx, Hy, Hz, Wx, Wy, Wz, Gx, Gy, Gz);
    }

    const float Mx = Hx - Gx, My = Hy - Gy, Mz = Hz - Gz;
    const float fx = Wx + Mx, fy = Wy + My, fz = Wz + Mz;
    const float dd = ujx * Mx + ujy * My + ujz * Mz;

    float* p = g_part + (size_t)s * 6 * NP;
    p[0*NP + j] = A1;
    p[1*NP + j] = A2;
    p[2*NP + j] = fx;
    p[3*NP + j] = fy;
    p[4*NP + j] = fz;
    p[5*NP + j] = dd;
}

// 96 blocks x 768 threads. tid = jl + 32*c + 192*slice.
// Thread (jl, c, slice) sums splits s = slice + 4*k (k=0..11), all unpredicated.
__global__ __launch_bounds__(TPB2)
void ewald_reduce_kernel(const float* __restrict__ q,
                         const float* __restrict__ kappa,
                         const float* __restrict__ alpha,
                         float* __restrict__ out)
{
    const int jl = threadIdx.x & 31;
    const int c  = (threadIdx.x >> 5) % 6;
    const int sl = threadIdx.x / 192;          // 0..3
    const int j  = blockIdx.x * RJ + jl;

    const float* base = g_part + (size_t)c * NP + j;
    float acc = 0.f;
#pragma unroll
    for (int k = 0; k < SPLITS / NSL; ++k)     // 12 independent unpredicated loads
        acc += base[(size_t)(sl + NSL * k) * 6 * NP];

    __shared__ float sh[NSL][6][RJ];
    sh[sl][c][jl] = acc;
    __syncthreads();

    if (threadIdx.x < 192) {   // slice 0: 6 warps combine the 4 slices
        sh[0][c][jl] = sh[0][c][jl] + sh[1][c][jl] + sh[2][c][jl] + sh[3][c][jl];
    }
    __syncthreads();

    float potj = 0.f;
    if (threadIdx.x < 32) {    // warp 0 does the per-j epilogue
        const float a1 = sh[0][0][jl], a2 = sh[0][1][jl];
        const float fx = sh[0][2][jl], fy = sh[0][3][jl], fz = sh[0][4][jl], dd = sh[0][5][jl];

        const float ka = kappa[j];
        const float al = alpha[j];
        const float qj = q[j];

        const float ephi = NC * (a1 + a2);
        const float qind = -ka * ephi;
        const float efx = NC * fx, efy = NC * fy, efz = NC * fz;

        out[1 + j] = qind;
        out[1 + NP + 3*j + 0] = al * efx;
        out[1 + NP + 3*j + 1] = al * efy;
        out[1 + NP + 3*j + 2] = al * efz;

        potj = qj * NC * (0.5f * a1 + a2)
             - 0.5f * NC * dd
             - 0.5f * ka * ephi * ephi
             - 0.5f * al * (efx * efx + efy * efy + efz * efz);

#pragma unroll
        for (int ofs = 16; ofs > 0; ofs >>= 1)
            potj += __shfl_down_sync(0xFFFFFFFFu, potj, ofs);
    }

    __shared__ bool lastblk;
    if (threadIdx.x == 0) {
        g_potblk[blockIdx.x] = potj;
        __threadfence();
        const int old = atomicAdd(&g_sem, 1);
        lastblk = (old == RBLK - 1);
    }
    __syncthreads();

    if (lastblk && threadIdx.x < 32) {
        __threadfence();
        const int t = threadIdx.x;
        // 96 = 3*32: each lane sums exactly 3 entries, then shuffle-reduce
        float v = g_potblk[t] + g_potblk[t + 32] + g_potblk[t + 64];
#pragma unroll
        for (int ofs = 16; ofs > 0; ofs >>= 1)
            v += __shfl_down_sync(0xFFFFFFFFu, v, ofs);
        if (t == 0) {
            out[0] = v;
            g_sem = 0;    // reset for next graph replay
        }
    }
}

extern "C" void kernel_launch(void* const* d_in, const int* in_sizes, int n_in,
                              void* d_out, int out_size)
{
    const float* q     = (const float*)d_in[0];
    const float* r     = (const float*)d_in[1];
    const float* u     = (const float*)d_in[4];
    const float* kappa = (const float*)d_in[5];
    const float* alpha = (const float*)d_in[6];
    float* out = (float*)d_out;

    dim3 grid1(JBLK, SPLITS);
    ewald_pair_kernel<<<grid1, TPB>>>(q, r, u);
    ewald_reduce_kernel<<<RBLK, TPB2>>>(q, kappa, alpha, out);
}

// round 13
// speedup vs baseline: 1.4250x; 1.0111x over previous
#include <cuda_runtime.h>

#define NP      3072
#define SPLITS  37
#define CHUNK   84              // 37*84 = 3108 >= 3072 (padded)
#define HC      (CHUNK / 2)     // 42 packed iterations
#define TPB     128
#define JBLK    (NP / TPB)      // 24 -> grid = 24*37 = 888 = 6*148 blocks

#define RJ      32              // j per reduce block
#define RBLK    (NP / RJ)       // 96 reduce blocks
#define NSL     4               // split-slices per (c,j)
#define TPB2    (RJ * 6 * NSL)  // 768 threads

// constants (sigma = 1, A = 1/sqrt(2), A^2 = 1/2)
#define A_CONST 0.7071067811865476f
#define C1      0.7978845608028654f     // 2A/sqrt(pi) == 4A^3/sqrt(pi) since A^2=1/2
#define NC      14.399645f              // 90.4756 / (2*pi)
// Abramowitz-Stegun 7.1.26 erfc: erfc(x) = g*t*P(t), t=1/(1+p*x), |err|<=1.5e-7
#define P_AS  0.3275911f
#define PA    (P_AS * A_CONST)
#define AS1   0.254829592f
#define AS2  -0.284496736f
#define AS3   1.421413741f
#define AS4  -1.453152027f
#define AS5   1.061405429f
#define NL2E_HALF (-0.7213475204444817f)  // -0.5*log2(e)
#define RCUT2     20.25f                   // beyond this erf=1,g=0 to ~1e-4 rel
#define RINV_CUT  0.2222f                  // 1/sqrt(RCUT2)

typedef unsigned long long u64;

__device__ float g_part[SPLITS * 6 * NP];
__device__ float g_potblk[RBLK];
__device__ int   g_sem;          // reset in-kernel after use

__device__ __forceinline__ float rcp_fast(float x) {
    float y; asm("rcp.approx.f32 %0, %1;" : "=f"(y) : "f"(x)); return y;
}
__device__ __forceinline__ float ex2_fast(float x) {
    float y; asm("ex2.approx.f32 %0, %1;" : "=f"(y) : "f"(x)); return y;
}
__device__ __forceinline__ u64 pk(float lo, float hi) {
    u64 r; asm("mov.b64 %0, {%1, %2};" : "=l"(r) : "f"(lo), "f"(hi)); return r;
}
__device__ __forceinline__ void upk(u64 a, float& lo, float& hi) {
    asm("mov.b64 {%0, %1}, %2;" : "=f"(lo), "=f"(hi) : "l"(a));
}
__device__ __forceinline__ u64 fma2(u64 a, u64 b, u64 c) {
    u64 d; asm("fma.rn.f32x2 %0, %1, %2, %3;" : "=l"(d) : "l"(a), "l"(b), "l"(c)); return d;
}
__device__ __forceinline__ u64 mul2(u64 a, u64 b) {
    u64 d; asm("mul.rn.f32x2 %0, %1, %2;" : "=l"(d) : "l"(a), "l"(b)); return d;
}
__device__ __forceinline__ u64 add2(u64 a, u64 b) {
    u64 d; asm("add.rn.f32x2 %0, %1, %2;" : "=l"(d) : "l"(a), "l"(b)); return d;
}

// scalar correction for one near pair: add (true - bare) terms; everything ~ g
__device__ __forceinline__ void corr_half(
    float dx, float dy, float dz, float qi,
    float ux, float uy, float uz, bool act,
    float& A1, float& A2,
    float& Hx, float& Hy, float& Hz,
    float& Wx, float& Wy, float& Wz,
    float& Gx, float& Gy, float& Gz)
{
    float t0 = dx * dx;
    t0 = fmaf(dy, dy, t0);
    const float d2 = fmaf(dz, dz, t0);
    const bool on = act && (d2 != 0.f) && (d2 < RCUT2);
    const float d2s  = fmaxf(d2, 1e-8f);
    const float rinv = rsqrtf(d2s);
    const float m    = on ? 1.f : 0.f;
    const float g    = ex2_fast(NL2E_HALF * d2s) * m;
    const float rn   = d2s * rinv;
    const float tt   = rcp_fast(fmaf(PA, rn, 1.f));
    const float poly = fmaf(fmaf(fmaf(fmaf(AS5, tt, AS4), tt, AS3), tt, AS2), tt, AS1);
    const float erfc = g * tt * poly;
    const float de   = -erfc * rinv;
    const float rr   = rinv * rinv;
    const float c1g  = C1 * g;
    const float ds1  = (de - c1g) * rr;
    const float uri  = fmaf(ux, dx, fmaf(uy, dy, uz * dz));
    const float ds2r = fmaf(3.f, ds1, -c1g) * (uri * rr);
    A1 = fmaf(qi, de, A1);
    A2 = fmaf(ds1, uri, A2);
    Hx = fmaf(ds2r, dx, Hx); Hy = fmaf(ds2r, dy, Hy); Hz = fmaf(ds2r, dz, Hz);
    const float qd = qi * ds1;
    Wx = fmaf(qd, dx, Wx); Wy = fmaf(qd, dy, Wy); Wz = fmaf(qd, dz, Wz);
    Gx = fmaf(ds1, ux, Gx); Gy = fmaf(ds1, uy, Gy); Gz = fmaf(ds1, uz, Gz);
}

__global__ __launch_bounds__(TPB, 6)
void ewald_pair_kernel(const float* __restrict__ q,
                       const float* __restrict__ r,
                       const float* __restrict__ u)
{
    const int j  = blockIdx.x * TPB + threadIdx.x;
    const int s  = blockIdx.y;
    const int i0 = s * CHUNK;

    __shared__ ulonglong2 s_p0[HC];   // {-rx2, -ry2}
    __shared__ ulonglong2 s_p1[HC];   // {-rz2,   q2}
    __shared__ ulonglong2 s_p2[HC];   // { ux2,  uy2}
    __shared__ u64        s_p3[HC];   // { uz2 }

    for (int t = threadIdx.x; t < HC; t += TPB) {
        const int ia = i0 + t;
        const int ib = ia + HC;
        float rxa, rya, rza, qa, uxa, uya, uza;
        float rxb, ryb, rzb, qb, uxb, uyb, uzb;
        if (ia < NP) {
            rxa = r[3*ia+0]; rya = r[3*ia+1]; rza = r[3*ia+2];
            qa = q[ia]; uxa = u[3*ia+0]; uya = u[3*ia+1]; uza = u[3*ia+2];
        } else { rxa=1e4f; rya=1e4f; rza=1e4f; qa=0.f; uxa=0.f; uya=0.f; uza=0.f; }
        if (ib < NP) {
            rxb = r[3*ib+0]; ryb = r[3*ib+1]; rzb = r[3*ib+2];
            qb = q[ib]; uxb = u[3*ib+0]; uyb = u[3*ib+1]; uzb = u[3*ib+2];
        } else { rxb=1e4f; ryb=1e4f; rzb=1e4f; qb=0.f; uxb=0.f; uyb=0.f; uzb=0.f; }
        s_p0[t] = make_ulonglong2(pk(-rxa, -rxb), pk(-rya, -ryb));
        s_p1[t] = make_ulonglong2(pk(-rza, -rzb), pk(qa, qb));
        s_p2[t] = make_ulonglong2(pk(uxa, uxb), pk(uya, uyb));
        s_p3[t] = pk(uza, uzb);
    }
    __syncthreads();

    const float rjx = r[3*j+0], rjy = r[3*j+1], rjz = r[3*j+2];
    const float ujx = u[3*j+0], ujy = u[3*j+1], ujz = u[3*j+2];

    const u64 rjx2 = pk(rjx, rjx), rjy2 = pk(rjy, rjy), rjz2 = pk(rjz, rjz);
    const u64 kThree = 0x4040000040400000ull;

    u64 a1 = 0, a2 = 0;
    u64 hx = 0, hy = 0, hz = 0;
    u64 wx = 0, wy = 0, wz = 0;
    u64 gx = 0, gy = 0, gz = 0;
    u64 mask = 0;

    // ---------------- Pass A: bare Coulomb (erf=1, g=0) for ALL pairs ----------------
#pragma unroll 6
    for (int t = 0; t < HC; ++t) {
        const ulonglong2 p0 = s_p0[t];
        const ulonglong2 p1 = s_p1[t];
        const ulonglong2 p2 = s_p2[t];
        const u64 uz2 = s_p3[t];

        const u64 dx = add2(rjx2, p0.x);
        const u64 dy = add2(rjy2, p0.y);
        const u64 dz = add2(rjz2, p1.x);
        u64 d2 = mul2(dx, dx);
        d2 = fma2(dy, dy, d2);
        d2 = fma2(dz, dz, d2);

        float d2l, d2h; upk(d2, d2l, d2h);
        float rl = rsqrtf(d2l), rh = rsqrtf(d2h);
        rl = (d2l == 0.f) ? 0.f : rl;
        rh = (d2h == 0.f) ? 0.f : rh;
        const bool near = fmaxf(rl, rh) > RINV_CUT;
        mask |= ((u64)near) << t;

        const u64 rinv = pk(rl, rh);
        const u64 rr   = mul2(rinv, rinv);
        const u64 s1   = mul2(rinv, rr);

        a1 = fma2(p1.y, rinv, a1);

        u64 uri = mul2(p2.x, dx);
        uri = fma2(p2.y, dy, uri);
        uri = fma2(uz2, dz, uri);
        a2 = fma2(s1, uri, a2);

        const u64 v   = mul2(uri, rr);
        const u64 v3  = mul2(v, kThree);
        const u64 s2r = mul2(s1, v3);

        hx = fma2(s2r, dx, hx);
        hy = fma2(s2r, dy, hy);
        hz = fma2(s2r, dz, hz);
        const u64 qs1 = mul2(p1.y, s1);
        wx = fma2(qs1, dx, wx);
        wy = fma2(qs1, dy, wy);
        wz = fma2(qs1, dz, wz);
        gx = fma2(s1, p2.x, gx);
        gy = fma2(s1, p2.y, gy);
        gz = fma2(s1, uz2, gz);
    }

    float l, h;
    upk(a1, l, h); float A1 = l + h;
    upk(a2, l, h); float A2 = l + h;
    upk(hx, l, h); float Hx = l + h;
    upk(hy, l, h); float Hy = l + h;
    upk(hz, l, h); float Hz = l + h;
    upk(wx, l, h); float Wx = l + h;
    upk(wy, l, h); float Wy = l + h;
    upk(wz, l, h); float Wz = l + h;
    upk(gx, l, h); float Gx = l + h;
    upk(gy, l, h); float Gy = l + h;
    upk(gz, l, h); float Gz = l + h;

    // ---------------- Pass B: sparse erf/gauss corrections for near pairs ----------------
    unsigned mlo = (unsigned)mask;
    unsigned mhi = (unsigned)(mask >> 32);
    while (__any_sync(0xFFFFFFFFu, mlo | mhi)) {
        const bool act = (mlo | mhi) != 0u;
        int t = 0;
        if (mlo) { t = __ffs(mlo) - 1;  mlo &= mlo - 1u; }
        else if (mhi) { t = __ffs(mhi) + 31; mhi &= mhi - 1u; }

        const ulonglong2 p0 = s_p0[t];
        const ulonglong2 p1 = s_p1[t];
        const ulonglong2 p2 = s_p2[t];
        const u64 uz2 = s_p3[t];
        float nrxl, nrxh, nryl, nryh, nrzl, nrzh, ql, qh;
        float uxl, uxh, uyl, uyh, uzl, uzh;
        upk(p0.x, nrxl, nrxh); upk(p0.y, nryl, nryh);
        upk(p1.x, nrzl, nrzh); upk(p1.y, ql, qh);
        upk(p2.x, uxl, uxh);   upk(p2.y, uyl, uyh);
        upk(uz2, uzl, uzh);

        corr_half(rjx + nrxl, rjy + nryl, rjz + nrzl, ql, uxl, uyl, uzl, act,
                  A1, A2, Hx, Hy, Hz, Wx, Wy, Wz, Gx, Gy, Gz);
        corr_half(rjx + nrxh, rjy + nryh, rjz + nrzh, qh, uxh, uyh, uzh, act,
                  A1, A2, Hx, Hy, Hz, Wx, Wy, Wz, Gx, Gy, Gz);
    }

    const float Mx = Hx - Gx, My = Hy - Gy, Mz = Hz - Gz;
    const float fx = Wx + Mx, fy = Wy + My, fz = Wz + Mz;
    const float dd = ujx * Mx + ujy * My + ujz * Mz;

    float* p = g_part + (size_t)s * 6 * NP;
    p[0*NP + j] = A1;
    p[1*NP + j] = A2;
    p[2*NP + j] = fx;
    p[3*NP + j] = fy;
    p[4*NP + j] = fz;
    p[5*NP + j] = dd;
}

// 96 blocks x 768 threads, PDL: prologue + input prefetch overlap the pair kernel,
// griddepcontrol.wait gates only the g_part reads.
__global__ __launch_bounds__(TPB2)
void ewald_reduce_kernel(const float* __restrict__ q,
                         const float* __restrict__ kappa,
                         const float* __restrict__ alpha,
                         float* __restrict__ out)
{
    const int jl = threadIdx.x & 31;
    const int c  = (threadIdx.x >> 5) % 6;
    const int sl = threadIdx.x / 192;          // 0..3
    const int j  = blockIdx.x * RJ + jl;

    // prefetch pair-independent inputs BEFORE waiting on the pair kernel
    float ka = 0.f, al = 0.f, qj = 0.f;
    if (threadIdx.x < 32) {
        ka = kappa[j]; al = alpha[j]; qj = q[j];
    }

    // wait for the pair kernel's completion (PDL); no-op under fallback launch
    asm volatile("griddepcontrol.wait;" ::: "memory");

    const float* base = g_part + (size_t)c * NP + j;
    float acc = 0.f;
#pragma unroll
    for (int k = 0; k < 9; ++k)                // 9 unpredicated loads: s = sl + 4k
        acc += base[(size_t)(sl + NSL * k) * 6 * NP];
    if (sl == 0)
        acc += base[(size_t)36 * 6 * NP];

    __shared__ float sh[NSL][6][RJ];
    sh[sl][c][jl] = acc;
    __syncthreads();

    if (threadIdx.x < 192) {   // slice 0: 6 warps combine the 4 slices
        sh[0][c][jl] = sh[0][c][jl] + sh[1][c][jl] + sh[2][c][jl] + sh[3][c][jl];
    }
    __syncthreads();

    float potj = 0.f;
    if (threadIdx.x < 32) {    // warp 0 does the per-j epilogue
        const float a1 = sh[0][0][jl], a2 = sh[0][1][jl];
        const float fx = sh[0][2][jl], fy = sh[0][3][jl], fz = sh[0][4][jl], dd = sh[0][5][jl];

        const float ephi = NC * (a1 + a2);
        const float qind = -ka * ephi;
        const float efx = NC * fx, efy = NC * fy, efz = NC * fz;

        out[1 + j] = qind;
        out[1 + NP + 3*j + 0] = al * efx;
        out[1 + NP + 3*j + 1] = al * efy;
        out[1 + NP + 3*j + 2] = al * efz;

        potj = qj * NC * (0.5f * a1 + a2)
             - 0.5f * NC * dd
             - 0.5f * ka * ephi * ephi
             - 0.5f * al * (efx * efx + efy * efy + efz * efz);

#pragma unroll
        for (int ofs = 16; ofs > 0; ofs >>= 1)
            potj += __shfl_down_sync(0xFFFFFFFFu, potj, ofs);
    }

    __shared__ bool lastblk;
    if (threadIdx.x == 0) {
        g_potblk[blockIdx.x] = potj;
        __threadfence();
        const int old = atomicAdd(&g_sem, 1);
        lastblk = (old == RBLK - 1);
    }
    __syncthreads();

    if (lastblk && threadIdx.x < 32) {
        __threadfence();
        const int t = threadIdx.x;
        // 96 = 3*32: each lane sums exactly 3 entries, then shuffle-reduce
        float v = g_potblk[t] + g_potblk[t + 32] + g_potblk[t + 64];
#pragma unroll
        for (int ofs = 16; ofs > 0; ofs >>= 1)
            v += __shfl_down_sync(0xFFFFFFFFu, v, ofs);
        if (t == 0) {
            out[0] = v;
            g_sem = 0;    // reset for next graph replay
        }
    }
}

extern "C" void kernel_launch(void* const* d_in, const int* in_sizes, int n_in,
                              void* d_out, int out_size)
{
    const float* q     = (const float*)d_in[0];
    const float* r     = (const float*)d_in[1];
    const float* u     = (const float*)d_in[4];
    const float* kappa = (const float*)d_in[5];
    const float* alpha = (const float*)d_in[6];
    float* out = (float*)d_out;

    dim3 grid1(JBLK, SPLITS);
    ewald_pair_kernel<<<grid1, TPB>>>(q, r, u);

    // reduce with programmatic dependent launch (overlap launch ramp + prologue
    // with the pair kernel); fall back to a plain launch if the attr is rejected.
    cudaLaunchConfig_t cfg = {};
    cfg.gridDim  = dim3(RBLK, 1, 1);
    cfg.blockDim = dim3(TPB2, 1, 1);
    cfg.dynamicSmemBytes = 0;
    cudaLaunchAttribute attrs[1];
    attrs[0].id = cudaLaunchAttributeProgrammaticStreamSerialization;
    attrs[0].val.programmaticStreamSerializationAllowed = 1;
    cfg.attrs = attrs;
    cfg.numAttrs = 1;

    cudaError_t e = cudaLaunchKernelEx(&cfg, ewald_reduce_kernel, q, kappa, alpha, out);
    if (e != cudaSuccess) {
        ewald_reduce_kernel<<<RBLK, TPB2>>>(q, kappa, alpha, out);
    }
}